// round 1
// baseline (speedup 1.0000x reference)
#include <cuda_runtime.h>
#include <math.h>
#include <stdint.h>

// ---------------- static device scratch (no allocation allowed) ----------------
__device__ float    g_xg1 [(size_t)32768 * 1024];   // layer1 input projection  (128 MB)
__device__ float    g_out1[(size_t)32768 * 256];    // layer1 hidden outputs    (32 MB)
__device__ float    g_xg2 [(size_t)32768 * 512];    // layer2 input projection  (64 MB)
__device__ float    g_h1  [2 * 64 * 256];           // double-buffered h, layer1
__device__ float    g_h2  [2 * 64 * 128];           // double-buffered h, layer2
__device__ unsigned g_bar1;
__device__ unsigned g_bar2;

// ---------------- helpers ----------------
__device__ __forceinline__ unsigned f2tf32(float f) {
    unsigned r;
    asm("cvt.rna.tf32.f32 %0, %1;" : "=r"(r) : "f"(f));
    return r;
}

__device__ __forceinline__ void mma_tf32(float* c, const unsigned* a, const unsigned* b) {
    asm volatile(
        "mma.sync.aligned.m16n8k8.row.col.f32.tf32.tf32.f32 "
        "{%0,%1,%2,%3},{%4,%5,%6,%7},{%8,%9},{%0,%1,%2,%3};"
        : "+f"(c[0]), "+f"(c[1]), "+f"(c[2]), "+f"(c[3])
        : "r"(a[0]), "r"(a[1]), "r"(a[2]), "r"(a[3]), "r"(b[0]), "r"(b[1]));
}

// ---------------- tf32 GEMM:  C[M,N] = A[M,K] * W[N,K]^T + b1[N] + b2[N] ----------------
// Block tile 128x64, BK=32, 8 warps (4 M x 2 N), warp tile 32x32 via m16n8k8.
__global__ void __launch_bounds__(256) gemm_tf32_bias(
    const float* __restrict__ A, const float* __restrict__ W,
    const float* __restrict__ b1, const float* __restrict__ b2,
    float* __restrict__ C, int M, int N, int K)
{
    __shared__ unsigned As[128 * 36];
    __shared__ unsigned Ws[64 * 36];

    const int tid  = threadIdx.x;
    const int lane = tid & 31, warp = tid >> 5;
    const int wm = warp & 3, wn = warp >> 2;       // warp grid 4x2
    const int g  = lane >> 2, tg = lane & 3;       // groupID / threadID_in_group
    const int bm = blockIdx.x * 128, bn = blockIdx.y * 64;

    float acc[2][4][4];
#pragma unroll
    for (int i = 0; i < 2; i++)
#pragma unroll
        for (int j = 0; j < 4; j++)
#pragma unroll
            for (int k = 0; k < 4; k++) acc[i][j][k] = 0.f;

    for (int kt = 0; kt < K; kt += 32) {
        // A tile: 128 rows x 32 cols = 1024 float4, 4 per thread
#pragma unroll
        for (int i = 0; i < 4; i++) {
            int f4 = tid + i * 256;
            int row = f4 >> 3, c4 = f4 & 7;
            float4 v = *(const float4*)(A + (size_t)(bm + row) * K + kt + c4 * 4);
            uint4 u = make_uint4(f2tf32(v.x), f2tf32(v.y), f2tf32(v.z), f2tf32(v.w));
            *(uint4*)(&As[row * 36 + c4 * 4]) = u;
        }
        // W tile: 64 rows x 32 cols = 512 float4, 2 per thread
#pragma unroll
        for (int i = 0; i < 2; i++) {
            int f4 = tid + i * 256;
            int row = f4 >> 3, c4 = f4 & 7;
            float4 v = *(const float4*)(W + (size_t)(bn + row) * K + kt + c4 * 4);
            uint4 u = make_uint4(f2tf32(v.x), f2tf32(v.y), f2tf32(v.z), f2tf32(v.w));
            *(uint4*)(&Ws[row * 36 + c4 * 4]) = u;
        }
        __syncthreads();

#pragma unroll
        for (int ks = 0; ks < 4; ks++) {
            unsigned af[2][4], bf[4][2];
#pragma unroll
            for (int mt = 0; mt < 2; mt++) {
                int r = wm * 32 + mt * 16 + g;
                af[mt][0] = As[(r)     * 36 + ks * 8 + tg];
                af[mt][1] = As[(r + 8) * 36 + ks * 8 + tg];
                af[mt][2] = As[(r)     * 36 + ks * 8 + tg + 4];
                af[mt][3] = As[(r + 8) * 36 + ks * 8 + tg + 4];
            }
#pragma unroll
            for (int nt = 0; nt < 4; nt++) {
                int nl = wn * 32 + nt * 8 + g;
                bf[nt][0] = Ws[nl * 36 + ks * 8 + tg];
                bf[nt][1] = Ws[nl * 36 + ks * 8 + tg + 4];
            }
#pragma unroll
            for (int mt = 0; mt < 2; mt++)
#pragma unroll
                for (int nt = 0; nt < 4; nt++)
                    mma_tf32(acc[mt][nt], af[mt], bf[nt]);
        }
        __syncthreads();
    }

    // epilogue: add bias, store fp32
#pragma unroll
    for (int mt = 0; mt < 2; mt++) {
        int r0 = bm + wm * 32 + mt * 16 + g;
#pragma unroll
        for (int nt = 0; nt < 4; nt++) {
            int c = bn + wn * 32 + nt * 8 + tg * 2;
            float bb0 = b1[c] + b2[c];
            float bb1 = b1[c + 1] + b2[c + 1];
            C[(size_t)r0 * N + c]           = acc[mt][nt][0] + bb0;
            C[(size_t)r0 * N + c + 1]       = acc[mt][nt][1] + bb1;
            C[(size_t)(r0 + 8) * N + c]     = acc[mt][nt][2] + bb0;
            C[(size_t)(r0 + 8) * N + c + 1] = acc[mt][nt][3] + bb1;
        }
    }
}

// ---------------- persistent LSTM recurrence ----------------
// HD = hidden size (= K of the recurrent matvec). Grid = HD/2 blocks, 512 threads.
// Thread (b, jl, gg): tid = b*8 + jl*4 + gg. Each thread computes one dot(h, Whh_row).
// Block owns 2 hidden columns (j = blockIdx.x*2 + jl), i.e. 8 gate rows, cached in SMEM.
// h is double-buffered in global; grid-wide sync via monotonic atomic counter.
template <int HD, bool STORE_OUT>
__global__ void __launch_bounds__(512, 1) lstm_recur(
    const float* __restrict__ xg,    // [64*T][4*HD], biases already included
    const float* __restrict__ Whh,   // [4*HD][HD]
    float* h_glob,                   // [2][64][HD]
    float* out,                      // [64*T][HD] or unused
    unsigned* bar, int T)
{
    constexpr int K4  = HD / 4;      // float4 per h row
    constexpr int HP4 = K4 + 1;      // padded (float4) row stride

    extern __shared__ float4 smem[];
    float4* h4 = smem;               // 64 * HP4
    float4* w4 = h4 + 64 * HP4;      // 8 * HP4
    float* gsh = (float*)(w4 + 8 * HP4);  // 512 floats

    const int tid = threadIdx.x;
    const int b   = tid >> 3;
    const int jl  = (tid >> 2) & 1;
    const int gg  = tid & 3;
    const int u   = tid >> 2;        // (b,jl) pair index, 0..127
    const int jbase = blockIdx.x * 2;
    const int nblk  = gridDim.x;

    // load this block's 8 weight rows into SMEM (rows ordered r = gg*2 + jl)
    for (int i = tid; i < 8 * K4; i += 512) {
        int r = i / K4, k4 = i - r * K4;
        int grow = (r >> 1) * HD + jbase + (r & 1);
        w4[r * HP4 + k4] = *(const float4*)(Whh + (size_t)grow * HD + k4 * 4);
    }
    const int wrow = gg * 2 + jl;

    float ccell = 0.f;  // cell state for updater threads (gg==0)

    for (int t = 0; t < T; t++) {
        const float* hread = h_glob + (size_t)(t & 1) * 64 * HD;
        float*       hwrit = h_glob + (size_t)((t + 1) & 1) * 64 * HD;

        // stage h (previous step, all 64 batches) into SMEM via L2-coherent loads
        for (int i = tid; i < 64 * K4; i += 512) {
            int bb = i / K4, k4 = i - bb * K4;
            h4[bb * HP4 + k4] = __ldcg((const float4*)hread + bb * K4 + k4);
        }
        __syncthreads();

        // dot(h[b,:], Whh[row,:])
        const float4* hp = h4 + b * HP4;
        const float4* wp = w4 + wrow * HP4;
        float s0 = 0.f, s1 = 0.f, s2 = 0.f, s3 = 0.f;
#pragma unroll 8
        for (int k = 0; k < K4; k++) {
            float4 hv = hp[k], wv = wp[k];
            s0 += hv.x * wv.x; s1 += hv.y * wv.y;
            s2 += hv.z * wv.z; s3 += hv.w * wv.w;
        }
        int j = jbase + jl;
        float pre = (s0 + s1) + (s2 + s3)
                  + xg[((size_t)b * T + t) * (4 * HD) + gg * HD + j];
        gsh[tid] = pre;
        __syncthreads();

        if (gg == 0) {
            float xi = gsh[u * 4 + 0];
            float xf = gsh[u * 4 + 1];
            float xc = gsh[u * 4 + 2];
            float xo = gsh[u * 4 + 3];
            float iv = 1.f / (1.f + __expf(-xi));
            float fv = 1.f / (1.f + __expf(-xf));
            float gv = tanhf(xc);
            float ov = 1.f / (1.f + __expf(-xo));
            ccell = fv * ccell + iv * gv;
            float h = ov * tanhf(ccell);
            int bu = u >> 1, ju = jbase + (u & 1);
            __stcg(hwrit + bu * HD + ju, h);
            if (STORE_OUT) out[((size_t)bu * T + t) * HD + ju] = h;
            __threadfence();
        }
        __syncthreads();

        // grid barrier: monotonic counter, target (t+1)*nblk
        if (tid == 0) {
            atomicAdd(bar, 1u);
            unsigned target = (unsigned)(t + 1) * (unsigned)nblk;
            while (*((volatile unsigned*)bar) < target) { __nanosleep(40); }
        }
        __syncthreads();
    }
}

// ---------------- FC head: out[b] = relu(h2[b]@Wfc^T + bfc) @ Wout^T + bout ----------------
__global__ void fc_head(const float* __restrict__ h2,     // [64][128] (buffer 0)
                        const float* __restrict__ Wfc,    // [64][128]
                        const float* __restrict__ bfc,    // [64]
                        const float* __restrict__ Wout,   // [1][64]
                        const float* __restrict__ bout,   // [1]
                        float* __restrict__ outp)         // [64]
{
    int b = threadIdx.x;  // 64 threads
    const float* hr = h2 + b * 128;
    float acc = 0.f;
    for (int uu = 0; uu < 64; uu++) {
        const float* wr = Wfc + uu * 128;
        float s0 = 0.f, s1 = 0.f, s2 = 0.f, s3 = 0.f;
#pragma unroll 8
        for (int k = 0; k < 128; k += 4) {
            s0 += hr[k]     * wr[k];
            s1 += hr[k + 1] * wr[k + 1];
            s2 += hr[k + 2] * wr[k + 2];
            s3 += hr[k + 3] * wr[k + 3];
        }
        float s = (s0 + s1) + (s2 + s3) + bfc[uu];
        acc += fmaxf(s, 0.f) * Wout[uu];
    }
    outp[b] = acc + bout[0];
}

// ---------------- launch ----------------
extern "C" void kernel_launch(void* const* d_in, const int* in_sizes, int n_in,
                              void* d_out, int out_size)
{
    const float* x    = (const float*)d_in[0];
    const float* Wih1 = (const float*)d_in[1];
    const float* Whh1 = (const float*)d_in[2];
    const float* bih1 = (const float*)d_in[3];
    const float* bhh1 = (const float*)d_in[4];
    const float* Wih2 = (const float*)d_in[5];
    const float* Whh2 = (const float*)d_in[6];
    const float* bih2 = (const float*)d_in[7];
    const float* bhh2 = (const float*)d_in[8];
    const float* Wfc1 = (const float*)d_in[9];
    const float* bfc1 = (const float*)d_in[10];
    const float* Wout = (const float*)d_in[11];
    const float* bout = (const float*)d_in[12];
    float* outp = (float*)d_out;

    float *xg1, *out1, *xg2, *h1, *h2;
    unsigned *bar1, *bar2;
    cudaGetSymbolAddress((void**)&xg1,  g_xg1);
    cudaGetSymbolAddress((void**)&out1, g_out1);
    cudaGetSymbolAddress((void**)&xg2,  g_xg2);
    cudaGetSymbolAddress((void**)&h1,   g_h1);
    cudaGetSymbolAddress((void**)&h2,   g_h2);
    cudaGetSymbolAddress((void**)&bar1, g_bar1);
    cudaGetSymbolAddress((void**)&bar2, g_bar2);

    // dynamic smem sizes for recurrence kernels
    const int SMEM1 = (64 * 65 + 8 * 65) * 16 + 512 * 4;  // HD=256: 76928 B
    const int SMEM2 = (64 * 33 + 8 * 33) * 16 + 512 * 4;  // HD=128: 40064 B
    cudaFuncSetAttribute(lstm_recur<256, true>,
                         cudaFuncAttributeMaxDynamicSharedMemorySize, 100 * 1024);
    cudaFuncSetAttribute(lstm_recur<128, false>,
                         cudaFuncAttributeMaxDynamicSharedMemorySize, 100 * 1024);

    cudaMemsetAsync(h1,   0, sizeof(float) * 2 * 64 * 256);
    cudaMemsetAsync(h2,   0, sizeof(float) * 2 * 64 * 128);
    cudaMemsetAsync(bar1, 0, sizeof(unsigned));
    cudaMemsetAsync(bar2, 0, sizeof(unsigned));

    const int M = 64 * 512;

    // layer 1 input projection: xg1 = x @ Wih1^T + bih1 + bhh1
    gemm_tf32_bias<<<dim3(M / 128, 1024 / 64), 256>>>(x, Wih1, bih1, bhh1, xg1,
                                                      M, 1024, 2048);
    // layer 1 recurrence (writes out1)
    lstm_recur<256, true><<<128, 512, SMEM1>>>(xg1, Whh1, h1, out1, bar1, 512);

    // layer 2 input projection: xg2 = out1 @ Wih2^T + bih2 + bhh2
    gemm_tf32_bias<<<dim3(M / 128, 512 / 64), 256>>>(out1, Wih2, bih2, bhh2, xg2,
                                                     M, 512, 256);
    // layer 2 recurrence (final h lands in buffer 0 of g_h2 after 512 steps)
    lstm_recur<128, false><<<64, 512, SMEM2>>>(xg2, Whh2, h2, (float*)0, bar2, 512);

    // FC head
    fc_head<<<1, 64>>>(h2, Wfc1, bfc1, Wout, bout, outp);
}

// round 2
// speedup vs baseline: 1.0035x; 1.0035x over previous
#include <cuda_runtime.h>
#include <math.h>
#include <stdint.h>

// ---------------- static device scratch (no allocation allowed) ----------------
__device__ float    g_xg1 [(size_t)32768 * 1024];   // layer1 input projection  (128 MB)
__device__ float    g_out1[(size_t)32768 * 256];    // layer1 hidden outputs    (32 MB)
__device__ float    g_xg2 [(size_t)32768 * 512];    // layer2 input projection  (64 MB)
__device__ float    g_h1  [2 * 64 * 256];           // double-buffered h, layer1
__device__ float    g_h2  [2 * 64 * 128];           // double-buffered h, layer2
__device__ unsigned g_bar1;
__device__ unsigned g_bar2;

// ---------------- helpers ----------------
__device__ __forceinline__ unsigned f2tf32(float f) {
    unsigned r;
    asm("cvt.rna.tf32.f32 %0, %1;" : "=r"(r) : "f"(f));
    return r;
}

__device__ __forceinline__ void mma_tf32(float* c, const unsigned* a, const unsigned* b) {
    asm volatile(
        "mma.sync.aligned.m16n8k8.row.col.f32.tf32.tf32.f32 "
        "{%0,%1,%2,%3},{%4,%5,%6,%7},{%8,%9},{%0,%1,%2,%3};"
        : "+f"(c[0]), "+f"(c[1]), "+f"(c[2]), "+f"(c[3])
        : "r"(a[0]), "r"(a[1]), "r"(a[2]), "r"(a[3]), "r"(b[0]), "r"(b[1]));
}

// ---------------- tf32 GEMM:  C[M,N] = A[M,K] * W[N,K]^T + b1[N] + b2[N] ----------------
// Block tile 128x64, BK=32, 8 warps (4 M x 2 N), warp tile 32x32 via m16n8k8.
__global__ void __launch_bounds__(256) gemm_tf32_bias(
    const float* __restrict__ A, const float* __restrict__ W,
    const float* __restrict__ b1, const float* __restrict__ b2,
    float* __restrict__ C, int M, int N, int K)
{
    __shared__ unsigned As[128 * 36];
    __shared__ unsigned Ws[64 * 36];

    const int tid  = threadIdx.x;
    const int lane = tid & 31, warp = tid >> 5;
    const int wm = warp & 3, wn = warp >> 2;       // warp grid 4x2
    const int g  = lane >> 2, tg = lane & 3;       // groupID / threadID_in_group
    const int bm = blockIdx.x * 128, bn = blockIdx.y * 64;

    float acc[2][4][4];
#pragma unroll
    for (int i = 0; i < 2; i++)
#pragma unroll
        for (int j = 0; j < 4; j++)
#pragma unroll
            for (int k = 0; k < 4; k++) acc[i][j][k] = 0.f;

    for (int kt = 0; kt < K; kt += 32) {
        // A tile: 128 rows x 32 cols = 1024 float4, 4 per thread
#pragma unroll
        for (int i = 0; i < 4; i++) {
            int f4 = tid + i * 256;
            int row = f4 >> 3, c4 = f4 & 7;
            float4 v = *(const float4*)(A + (size_t)(bm + row) * K + kt + c4 * 4);
            uint4 u = make_uint4(f2tf32(v.x), f2tf32(v.y), f2tf32(v.z), f2tf32(v.w));
            *(uint4*)(&As[row * 36 + c4 * 4]) = u;
        }
        // W tile: 64 rows x 32 cols = 512 float4, 2 per thread
#pragma unroll
        for (int i = 0; i < 2; i++) {
            int f4 = tid + i * 256;
            int row = f4 >> 3, c4 = f4 & 7;
            float4 v = *(const float4*)(W + (size_t)(bn + row) * K + kt + c4 * 4);
            uint4 u = make_uint4(f2tf32(v.x), f2tf32(v.y), f2tf32(v.z), f2tf32(v.w));
            *(uint4*)(&Ws[row * 36 + c4 * 4]) = u;
        }
        __syncthreads();

#pragma unroll
        for (int ks = 0; ks < 4; ks++) {
            unsigned af[2][4], bf[4][2];
#pragma unroll
            for (int mt = 0; mt < 2; mt++) {
                int r = wm * 32 + mt * 16 + g;
                af[mt][0] = As[(r)     * 36 + ks * 8 + tg];
                af[mt][1] = As[(r + 8) * 36 + ks * 8 + tg];
                af[mt][2] = As[(r)     * 36 + ks * 8 + tg + 4];
                af[mt][3] = As[(r + 8) * 36 + ks * 8 + tg + 4];
            }
#pragma unroll
            for (int nt = 0; nt < 4; nt++) {
                int nl = wn * 32 + nt * 8 + g;
                bf[nt][0] = Ws[nl * 36 + ks * 8 + tg];
                bf[nt][1] = Ws[nl * 36 + ks * 8 + tg + 4];
            }
#pragma unroll
            for (int mt = 0; mt < 2; mt++)
#pragma unroll
                for (int nt = 0; nt < 4; nt++)
                    mma_tf32(acc[mt][nt], af[mt], bf[nt]);
        }
        __syncthreads();
    }

    // epilogue: add bias, store fp32
#pragma unroll
    for (int mt = 0; mt < 2; mt++) {
        int r0 = bm + wm * 32 + mt * 16 + g;
#pragma unroll
        for (int nt = 0; nt < 4; nt++) {
            int c = bn + wn * 32 + nt * 8 + tg * 2;
            float bb0 = b1[c] + b2[c];
            float bb1 = b1[c + 1] + b2[c + 1];
            C[(size_t)r0 * N + c]           = acc[mt][nt][0] + bb0;
            C[(size_t)r0 * N + c + 1]       = acc[mt][nt][1] + bb1;
            C[(size_t)(r0 + 8) * N + c]     = acc[mt][nt][2] + bb0;
            C[(size_t)(r0 + 8) * N + c + 1] = acc[mt][nt][3] + bb1;
        }
    }
}

// ---------------- persistent LSTM recurrence ----------------
// HD = hidden size (= K of the recurrent matvec). Grid = HD/2 blocks, 512 threads.
// Thread (b, jl, gg): tid = b*8 + jl*4 + gg. Each thread computes one dot(h, Whh_row).
// Block owns 2 hidden columns (j = blockIdx.x*2 + jl), i.e. 8 gate rows, cached in SMEM.
// h is double-buffered in global; grid-wide sync via monotonic atomic counter.
template <int HD, bool STORE_OUT>
__global__ void __launch_bounds__(512, 1) lstm_recur(
    const float* __restrict__ xg,    // [64*T][4*HD], biases already included
    const float* __restrict__ Whh,   // [4*HD][HD]
    float* h_glob,                   // [2][64][HD]
    float* out,                      // [64*T][HD] or unused
    unsigned* bar, int T)
{
    constexpr int K4  = HD / 4;      // float4 per h row
    constexpr int HP4 = K4 + 1;      // padded (float4) row stride

    extern __shared__ float4 smem[];
    float4* h4 = smem;               // 64 * HP4
    float4* w4 = h4 + 64 * HP4;      // 8 * HP4
    float* gsh = (float*)(w4 + 8 * HP4);  // 512 floats

    const int tid = threadIdx.x;
    const int b   = tid >> 3;
    const int jl  = (tid >> 2) & 1;
    const int gg  = tid & 3;
    const int u   = tid >> 2;        // (b,jl) pair index, 0..127
    const int jbase = blockIdx.x * 2;
    const int nblk  = gridDim.x;

    // load this block's 8 weight rows into SMEM (rows ordered r = gg*2 + jl)
    for (int i = tid; i < 8 * K4; i += 512) {
        int r = i / K4, k4 = i - r * K4;
        int grow = (r >> 1) * HD + jbase + (r & 1);
        w4[r * HP4 + k4] = *(const float4*)(Whh + (size_t)grow * HD + k4 * 4);
    }
    const int wrow = gg * 2 + jl;

    float ccell = 0.f;  // cell state for updater threads (gg==0)

    for (int t = 0; t < T; t++) {
        const float* hread = h_glob + (size_t)(t & 1) * 64 * HD;
        float*       hwrit = h_glob + (size_t)((t + 1) & 1) * 64 * HD;

        // stage h (previous step, all 64 batches) into SMEM via L2-coherent loads
        for (int i = tid; i < 64 * K4; i += 512) {
            int bb = i / K4, k4 = i - bb * K4;
            h4[bb * HP4 + k4] = __ldcg((const float4*)hread + bb * K4 + k4);
        }
        __syncthreads();

        // dot(h[b,:], Whh[row,:])
        const float4* hp = h4 + b * HP4;
        const float4* wp = w4 + wrow * HP4;
        float s0 = 0.f, s1 = 0.f, s2 = 0.f, s3 = 0.f;
#pragma unroll 8
        for (int k = 0; k < K4; k++) {
            float4 hv = hp[k], wv = wp[k];
            s0 += hv.x * wv.x; s1 += hv.y * wv.y;
            s2 += hv.z * wv.z; s3 += hv.w * wv.w;
        }
        int j = jbase + jl;
        float pre = (s0 + s1) + (s2 + s3)
                  + xg[((size_t)b * T + t) * (4 * HD) + gg * HD + j];
        gsh[tid] = pre;
        __syncthreads();

        if (gg == 0) {
            float xi = gsh[u * 4 + 0];
            float xf = gsh[u * 4 + 1];
            float xc = gsh[u * 4 + 2];
            float xo = gsh[u * 4 + 3];
            float iv = 1.f / (1.f + __expf(-xi));
            float fv = 1.f / (1.f + __expf(-xf));
            float gv = tanhf(xc);
            float ov = 1.f / (1.f + __expf(-xo));
            ccell = fv * ccell + iv * gv;
            float h = ov * tanhf(ccell);
            int bu = u >> 1, ju = jbase + (u & 1);
            __stcg(hwrit + bu * HD + ju, h);
            if (STORE_OUT) out[((size_t)bu * T + t) * HD + ju] = h;
            __threadfence();
        }
        __syncthreads();

        // grid barrier: monotonic counter, target (t+1)*nblk
        if (tid == 0) {
            atomicAdd(bar, 1u);
            unsigned target = (unsigned)(t + 1) * (unsigned)nblk;
            while (*((volatile unsigned*)bar) < target) { __nanosleep(40); }
        }
        __syncthreads();
    }
}

// ---------------- FC head: out[b] = relu(h2[b]@Wfc^T + bfc) @ Wout^T + bout ----------------
__global__ void fc_head(const float* __restrict__ h2,     // [64][128] (buffer 0)
                        const float* __restrict__ Wfc,    // [64][128]
                        const float* __restrict__ bfc,    // [64]
                        const float* __restrict__ Wout,   // [1][64]
                        const float* __restrict__ bout,   // [1]
                        float* __restrict__ outp)         // [64]
{
    int b = threadIdx.x;  // 64 threads
    const float* hr = h2 + b * 128;
    float acc = 0.f;
    for (int uu = 0; uu < 64; uu++) {
        const float* wr = Wfc + uu * 128;
        float s0 = 0.f, s1 = 0.f, s2 = 0.f, s3 = 0.f;
#pragma unroll 8
        for (int k = 0; k < 128; k += 4) {
            s0 += hr[k]     * wr[k];
            s1 += hr[k + 1] * wr[k + 1];
            s2 += hr[k + 2] * wr[k + 2];
            s3 += hr[k + 3] * wr[k + 3];
        }
        float s = (s0 + s1) + (s2 + s3) + bfc[uu];
        acc += fmaxf(s, 0.f) * Wout[uu];
    }
    outp[b] = acc + bout[0];
}

// ---------------- launch ----------------
extern "C" void kernel_launch(void* const* d_in, const int* in_sizes, int n_in,
                              void* d_out, int out_size)
{
    const float* x    = (const float*)d_in[0];
    const float* Wih1 = (const float*)d_in[1];
    const float* Whh1 = (const float*)d_in[2];
    const float* bih1 = (const float*)d_in[3];
    const float* bhh1 = (const float*)d_in[4];
    const float* Wih2 = (const float*)d_in[5];
    const float* Whh2 = (const float*)d_in[6];
    const float* bih2 = (const float*)d_in[7];
    const float* bhh2 = (const float*)d_in[8];
    const float* Wfc1 = (const float*)d_in[9];
    const float* bfc1 = (const float*)d_in[10];
    const float* Wout = (const float*)d_in[11];
    const float* bout = (const float*)d_in[12];
    float* outp = (float*)d_out;

    float *xg1, *out1, *xg2, *h1, *h2;
    unsigned *bar1, *bar2;
    cudaGetSymbolAddress((void**)&xg1,  g_xg1);
    cudaGetSymbolAddress((void**)&out1, g_out1);
    cudaGetSymbolAddress((void**)&xg2,  g_xg2);
    cudaGetSymbolAddress((void**)&h1,   g_h1);
    cudaGetSymbolAddress((void**)&h2,   g_h2);
    cudaGetSymbolAddress((void**)&bar1, g_bar1);
    cudaGetSymbolAddress((void**)&bar2, g_bar2);

    // dynamic smem sizes for recurrence kernels
    const int SMEM1 = (64 * 65 + 8 * 65) * 16 + 512 * 4;  // HD=256: 76928 B
    const int SMEM2 = (64 * 33 + 8 * 33) * 16 + 512 * 4;  // HD=128: 40064 B
    cudaFuncSetAttribute(lstm_recur<256, true>,
                         cudaFuncAttributeMaxDynamicSharedMemorySize, 100 * 1024);
    cudaFuncSetAttribute(lstm_recur<128, false>,
                         cudaFuncAttributeMaxDynamicSharedMemorySize, 100 * 1024);

    cudaMemsetAsync(h1,   0, sizeof(float) * 2 * 64 * 256);
    cudaMemsetAsync(h2,   0, sizeof(float) * 2 * 64 * 128);
    cudaMemsetAsync(bar1, 0, sizeof(unsigned));
    cudaMemsetAsync(bar2, 0, sizeof(unsigned));

    const int M = 64 * 512;

    // layer 1 input projection: xg1 = x @ Wih1^T + bih1 + bhh1
    gemm_tf32_bias<<<dim3(M / 128, 1024 / 64), 256>>>(x, Wih1, bih1, bhh1, xg1,
                                                      M, 1024, 2048);
    // layer 1 recurrence (writes out1)
    lstm_recur<256, true><<<128, 512, SMEM1>>>(xg1, Whh1, h1, out1, bar1, 512);

    // layer 2 input projection: xg2 = out1 @ Wih2^T + bih2 + bhh2
    gemm_tf32_bias<<<dim3(M / 128, 512 / 64), 256>>>(out1, Wih2, bih2, bhh2, xg2,
                                                     M, 512, 256);
    // layer 2 recurrence (final h lands in buffer 0 of g_h2 after 512 steps)
    lstm_recur<128, false><<<64, 512, SMEM2>>>(xg2, Whh2, h2, (float*)0, bar2, 512);

    // FC head
    fc_head<<<1, 64>>>(h2, Wfc1, bfc1, Wout, bout, outp);
}

// round 3
// speedup vs baseline: 1.4350x; 1.4300x over previous
#include <cuda_runtime.h>
#include <math.h>
#include <stdint.h>

// ---------------- static device scratch (no allocation allowed) ----------------
__device__ float    g_xg1 [(size_t)32768 * 1024];   // layer1 input projection, layout [b][t][j*4+g]
__device__ float    g_out1[(size_t)32768 * 256];    // layer1 hidden outputs [b][t][j] (tf32-rounded)
__device__ float    g_xg2 [(size_t)32768 * 512];    // layer2 input projection [b][t][j*4+g]
__device__ float    g_w1cv[(size_t)1024 * 2048];    // Wih1 rounded to tf32
__device__ float    g_w2cv[(size_t)512 * 256];      // Wih2 rounded to tf32
__device__ float    g_h1  [2 * 64 * 256];           // double-buffered h, layer1
__device__ float    g_h2  [2 * 64 * 128];           // double-buffered h, layer2
__device__ unsigned g_bar1;
__device__ unsigned g_bar2;

// ---------------- helpers ----------------
__device__ __forceinline__ unsigned f2tf32(float f) {
    unsigned r;
    asm("cvt.rna.tf32.f32 %0, %1;" : "=r"(r) : "f"(f));
    return r;
}

__device__ __forceinline__ void mma_tf32(float* c, const unsigned* a, const unsigned* b) {
    asm volatile(
        "mma.sync.aligned.m16n8k8.row.col.f32.tf32.tf32.f32 "
        "{%0,%1,%2,%3},{%4,%5,%6,%7},{%8,%9},{%0,%1,%2,%3};"
        : "+f"(c[0]), "+f"(c[1]), "+f"(c[2]), "+f"(c[3])
        : "r"(a[0]), "r"(a[1]), "r"(a[2]), "r"(a[3]), "r"(b[0]), "r"(b[1]));
}

__device__ __forceinline__ void cp_async16(void* smem_dst, const void* gptr) {
    unsigned s = (unsigned)__cvta_generic_to_shared(smem_dst);
    asm volatile("cp.async.cg.shared.global [%0], [%1], 16;\n" :: "r"(s), "l"(gptr));
}
#define CP_COMMIT() asm volatile("cp.async.commit_group;\n" ::: "memory")
#define CP_WAIT0()  asm volatile("cp.async.wait_group 0;\n" ::: "memory")

// ---------------- prep: round weights to tf32 once ----------------
__global__ void cvt_rna_kernel(const float* __restrict__ src, float* __restrict__ dst, int n) {
    int i = blockIdx.x * 256 + threadIdx.x;
    if (i < n) dst[i] = __uint_as_float(f2tf32(src[i]));
}

// ---------------- tf32 GEMM with permuted output columns ----------------
// C[m][n'] = sum_k A[m][k] * W[srcrow(n')][k] + bias(srcrow(n'))
// n' = j*4+g maps to source row g*H + j (H = N/4). Biases b1+b2 added.
// Tiles: 128M x 128N x 32K, 256 threads, double-buffered cp.async.
__global__ void __launch_bounds__(256, 2) gemm_tf32_perm(
    const float* __restrict__ A, const float* __restrict__ W,
    const float* __restrict__ b1, const float* __restrict__ b2,
    float* __restrict__ C, int M, int N, int K)
{
    extern __shared__ unsigned sh[];
    unsigned* As = sh;                 // [2][128][36]
    unsigned* Bs = sh + 2 * 128 * 36;  // [2][128][36]

    const int tid = threadIdx.x, lane = tid & 31, warp = tid >> 5;
    const int wm = warp & 1, wn = warp >> 1;   // 2 x 4 warp grid, warp tile 64x32
    const int g = lane >> 2, tg = lane & 3;
    const int bn = blockIdx.x * 128, bm = blockIdx.y * 128;
    const int H = N >> 2;

    float acc[4][4][4];
#pragma unroll
    for (int a = 0; a < 4; a++)
#pragma unroll
        for (int b = 0; b < 4; b++)
#pragma unroll
            for (int c = 0; c < 4; c++) acc[a][b][c] = 0.f;

    const int NK = K >> 5;

    // prologue: tile 0
#pragma unroll
    for (int i = 0; i < 4; i++) {
        int id = tid + i * 256, row = id >> 3, c4 = id & 7;
        cp_async16(&As[row * 36 + c4 * 4], A + (size_t)(bm + row) * K + c4 * 4);
        int np = bn + row;
        int srow = (np & 3) * H + (np >> 2);
        cp_async16(&Bs[row * 36 + c4 * 4], W + (size_t)srow * K + c4 * 4);
    }
    CP_COMMIT();

    int buf = 0;
    for (int kt = 0; kt < NK; kt++) {
        CP_WAIT0();
        __syncthreads();
        if (kt + 1 < NK) {
            int koff = (kt + 1) * 32;
            int nb = buf ^ 1;
#pragma unroll
            for (int i = 0; i < 4; i++) {
                int id = tid + i * 256, row = id >> 3, c4 = id & 7;
                cp_async16(&As[nb * 128 * 36 + row * 36 + c4 * 4],
                           A + (size_t)(bm + row) * K + koff + c4 * 4);
                int np = bn + row;
                int srow = (np & 3) * H + (np >> 2);
                cp_async16(&Bs[nb * 128 * 36 + row * 36 + c4 * 4],
                           W + (size_t)srow * K + koff + c4 * 4);
            }
        }
        CP_COMMIT();

        const unsigned* Ab = As + buf * 128 * 36;
        const unsigned* Bb = Bs + buf * 128 * 36;
#pragma unroll
        for (int ks = 0; ks < 4; ks++) {
            unsigned af[4][4], bf[4][2];
#pragma unroll
            for (int mt = 0; mt < 4; mt++) {
                int r = wm * 64 + mt * 16 + g;
                af[mt][0] = Ab[r * 36 + ks * 8 + tg];
                af[mt][1] = Ab[(r + 8) * 36 + ks * 8 + tg];
                af[mt][2] = Ab[r * 36 + ks * 8 + tg + 4];
                af[mt][3] = Ab[(r + 8) * 36 + ks * 8 + tg + 4];
            }
#pragma unroll
            for (int nt = 0; nt < 4; nt++) {
                int nl = wn * 32 + nt * 8 + g;
                bf[nt][0] = Bb[nl * 36 + ks * 8 + tg];
                bf[nt][1] = Bb[nl * 36 + ks * 8 + tg + 4];
            }
#pragma unroll
            for (int mt = 0; mt < 4; mt++)
#pragma unroll
                for (int nt = 0; nt < 4; nt++)
                    mma_tf32(acc[mt][nt], af[mt], bf[nt]);
        }
        buf ^= 1;
    }

    // epilogue: permuted bias + store
#pragma unroll
    for (int mt = 0; mt < 4; mt++) {
        int r0 = bm + wm * 64 + mt * 16 + g;
#pragma unroll
        for (int nt = 0; nt < 4; nt++) {
            int c = bn + wn * 32 + nt * 8 + tg * 2;
            int s0 = (c & 3) * H + (c >> 2);
            int s1 = ((c + 1) & 3) * H + ((c + 1) >> 2);
            float bb0 = b1[s0] + b2[s0];
            float bb1 = b1[s1] + b2[s1];
            C[(size_t)r0 * N + c]           = acc[mt][nt][0] + bb0;
            C[(size_t)r0 * N + c + 1]       = acc[mt][nt][1] + bb1;
            C[(size_t)(r0 + 8) * N + c]     = acc[mt][nt][2] + bb0;
            C[(size_t)(r0 + 8) * N + c + 1] = acc[mt][nt][3] + bb1;
        }
    }
}

// ---------------- persistent LSTM recurrence on tensor cores ----------------
// Grid = HD/2 blocks x 256 threads. Block owns 2 hidden cols (jbase, jbase+1)
// = 8 gate rows, ordered c = jl*4+g. Per step: C[64][8] = h[64][HD] * w[8][HD]^T
// via m16n8k8 tf32; warps: mt = warp&3 (16-batch m-tile), kh = warp>>2 (k half).
// Partials reduced in SMEM; 128 updater threads do the cell update.
template <int HD, bool STORE_OUT>
__global__ void __launch_bounds__(256, 1) lstm_recur_mma(
    const float* __restrict__ xg,    // [b][t][j*4+g]
    const float* __restrict__ Whh,   // [4*HD][HD]
    float* h_glob,                   // [2][64][HD]
    float* out,                      // [b][t][HD] or unused
    unsigned* bar, int T)
{
    constexpr int HP = HD + 4;       // padded uint stride (HP%32==4 -> conflict-free frags)
    constexpr int KSTEPS = HD / 16;  // mma k-steps per warp (per k-half)
    constexpr int C4 = HD / 4;

    extern __shared__ unsigned smem_u[];
    unsigned* hs = smem_u;                     // [64][HP] tf32 h
    unsigned* ws = hs + 64 * HP;               // [8][HP]  tf32 weights
    float* part  = (float*)(ws + 8 * HP);      // [2][64][12]

    const int tid = threadIdx.x, lane = tid & 31, warp = tid >> 5;
    const int mt = warp & 3, kh = warp >> 2;
    const int g = lane >> 2, tg = lane & 3;
    const int jbase = blockIdx.x * 2;
    const int nblk = gridDim.x;

    // load + round this block's 8 weight rows; C col c=jl*4+g -> src row g*HD + jbase + jl
    for (int i = tid; i < 8 * HD; i += 256) {
        int c = i / HD, k = i & (HD - 1);
        int srow = (c & 3) * HD + jbase + (c >> 2);
        ws[c * HP + k] = f2tf32(Whh[(size_t)srow * HD + k]);
    }

    const int ub = tid >> 1, ujl = tid & 1;    // updater mapping (tid<128)
    float cc = 0.f;
    const float* xgp = xg + (size_t)(tid < 128 ? ub : 0) * T * (4 * HD) + (jbase + ujl) * 4;

    for (int t = 0; t < T; t++) {
        const float* hread = h_glob + (size_t)(t & 1) * 64 * HD;
        float*       hwrit = h_glob + (size_t)((t + 1) & 1) * 64 * HD;

        // stage previous h (all batches) into SMEM as tf32
        const float4* hr4 = (const float4*)hread;
        for (int i = tid; i < 64 * C4; i += 256) {
            int b = i / C4, k4 = i & (C4 - 1);
            float4 v = __ldcg(hr4 + i);
            uint4 u = make_uint4(f2tf32(v.x), f2tf32(v.y), f2tf32(v.z), f2tf32(v.w));
            *(uint4*)(hs + b * HP + k4 * 4) = u;
        }
        __syncthreads();

        // mma: two independent accumulator chains
        float accA[4] = {0.f, 0.f, 0.f, 0.f};
        float accB[4] = {0.f, 0.f, 0.f, 0.f};
        const unsigned* hrow  = hs + (mt * 16 + g) * HP + kh * (HD / 2);
        const unsigned* hrow8 = hrow + 8 * HP;
        const unsigned* wrow  = ws + g * HP + kh * (HD / 2);
#pragma unroll
        for (int ks = 0; ks < KSTEPS; ks++) {
            unsigned af[4], bfr[2];
            int c = ks * 8 + tg;
            af[0] = hrow[c]; af[1] = hrow8[c]; af[2] = hrow[c + 4]; af[3] = hrow8[c + 4];
            bfr[0] = wrow[c]; bfr[1] = wrow[c + 4];
            mma_tf32((ks & 1) ? accB : accA, af, bfr);
        }
        int prow = mt * 16 + g;
        part[(kh * 64 + prow) * 12 + 2 * tg]         = accA[0] + accB[0];
        part[(kh * 64 + prow) * 12 + 2 * tg + 1]     = accA[1] + accB[1];
        part[(kh * 64 + prow + 8) * 12 + 2 * tg]     = accA[2] + accB[2];
        part[(kh * 64 + prow + 8) * 12 + 2 * tg + 1] = accA[3] + accB[3];
        __syncthreads();

        if (tid < 128) {
            float4 p0 = *(const float4*)(part + (size_t)ub * 12 + ujl * 4);
            float4 p1 = *(const float4*)(part + (size_t)(64 + ub) * 12 + ujl * 4);
            float4 xv = *(const float4*)(xgp + (size_t)t * (4 * HD));
            float gi = p0.x + p1.x + xv.x;
            float gf = p0.y + p1.y + xv.y;
            float gc = p0.z + p1.z + xv.z;
            float go = p0.w + p1.w + xv.w;
            float iv = 1.f / (1.f + __expf(-gi));
            float fv = 1.f / (1.f + __expf(-gf));
            float gv = tanhf(gc);
            float ov = 1.f / (1.f + __expf(-go));
            cc = fv * cc + iv * gv;
            float h = ov * tanhf(cc);
            float hr = __uint_as_float(f2tf32(h));   // tf32-rounded so downstream truncation is exact
            __stcg(hwrit + ub * HD + jbase + ujl, hr);
            if (STORE_OUT) out[((size_t)ub * T + t) * HD + jbase + ujl] = hr;
            __threadfence();
        }
        __syncthreads();

        if (tid == 0) {
            atomicAdd(bar, 1u);
            unsigned tgt = (unsigned)(t + 1) * (unsigned)nblk;
            while (*(volatile unsigned*)bar < tgt) { __nanosleep(20); }
        }
        __syncthreads();
    }
}

// ---------------- FC head ----------------
__global__ void fc_head(const float* __restrict__ h2,     // [64][128] (buffer 0)
                        const float* __restrict__ Wfc,    // [64][128]
                        const float* __restrict__ bfc,    // [64]
                        const float* __restrict__ Wout,   // [1][64]
                        const float* __restrict__ bout,   // [1]
                        float* __restrict__ outp)         // [64]
{
    int b = threadIdx.x;  // 64 threads
    const float* hr = h2 + b * 128;
    float acc = 0.f;
    for (int uu = 0; uu < 64; uu++) {
        const float* wr = Wfc + uu * 128;
        float s0 = 0.f, s1 = 0.f, s2 = 0.f, s3 = 0.f;
#pragma unroll 8
        for (int k = 0; k < 128; k += 4) {
            s0 += hr[k]     * wr[k];
            s1 += hr[k + 1] * wr[k + 1];
            s2 += hr[k + 2] * wr[k + 2];
            s3 += hr[k + 3] * wr[k + 3];
        }
        float s = (s0 + s1) + (s2 + s3) + bfc[uu];
        acc += fmaxf(s, 0.f) * Wout[uu];
    }
    outp[b] = acc + bout[0];
}

// ---------------- launch ----------------
extern "C" void kernel_launch(void* const* d_in, const int* in_sizes, int n_in,
                              void* d_out, int out_size)
{
    const float* x    = (const float*)d_in[0];
    const float* Wih1 = (const float*)d_in[1];
    const float* Whh1 = (const float*)d_in[2];
    const float* bih1 = (const float*)d_in[3];
    const float* bhh1 = (const float*)d_in[4];
    const float* Wih2 = (const float*)d_in[5];
    const float* Whh2 = (const float*)d_in[6];
    const float* bih2 = (const float*)d_in[7];
    const float* bhh2 = (const float*)d_in[8];
    const float* Wfc1 = (const float*)d_in[9];
    const float* bfc1 = (const float*)d_in[10];
    const float* Wout = (const float*)d_in[11];
    const float* bout = (const float*)d_in[12];
    float* outp = (float*)d_out;

    float *xg1, *out1, *xg2, *w1cv, *w2cv, *h1, *h2;
    unsigned *bar1, *bar2;
    cudaGetSymbolAddress((void**)&xg1,  g_xg1);
    cudaGetSymbolAddress((void**)&out1, g_out1);
    cudaGetSymbolAddress((void**)&xg2,  g_xg2);
    cudaGetSymbolAddress((void**)&w1cv, g_w1cv);
    cudaGetSymbolAddress((void**)&w2cv, g_w2cv);
    cudaGetSymbolAddress((void**)&h1,   g_h1);
    cudaGetSymbolAddress((void**)&h2,   g_h2);
    cudaGetSymbolAddress((void**)&bar1, g_bar1);
    cudaGetSymbolAddress((void**)&bar2, g_bar2);

    const int GEMM_SMEM = 2 * 128 * 36 * 4 * 2;            // 73728 B
    const int R1_SMEM = (64 * 260 + 8 * 260) * 4 + 2 * 64 * 12 * 4;  // 81024 B
    const int R2_SMEM = (64 * 132 + 8 * 132) * 4 + 2 * 64 * 12 * 4;  // 44160 B
    cudaFuncSetAttribute(gemm_tf32_perm,
                         cudaFuncAttributeMaxDynamicSharedMemorySize, GEMM_SMEM);
    cudaFuncSetAttribute(lstm_recur_mma<256, true>,
                         cudaFuncAttributeMaxDynamicSharedMemorySize, R1_SMEM);
    cudaFuncSetAttribute(lstm_recur_mma<128, false>,
                         cudaFuncAttributeMaxDynamicSharedMemorySize, R2_SMEM);

    cudaMemsetAsync(h1,   0, sizeof(float) * 2 * 64 * 256);
    cudaMemsetAsync(h2,   0, sizeof(float) * 2 * 64 * 128);
    cudaMemsetAsync(bar1, 0, sizeof(unsigned));
    cudaMemsetAsync(bar2, 0, sizeof(unsigned));

    // prep: round input-projection weights to tf32
    cvt_rna_kernel<<<(1024 * 2048 + 255) / 256, 256>>>(Wih1, w1cv, 1024 * 2048);
    cvt_rna_kernel<<<(512 * 256 + 255) / 256, 256>>>(Wih2, w2cv, 512 * 256);

    const int M = 64 * 512;

    // layer 1 input projection (n-tiles fastest for A reuse in L2)
    gemm_tf32_perm<<<dim3(1024 / 128, M / 128), 256, GEMM_SMEM>>>(
        x, w1cv, bih1, bhh1, xg1, M, 1024, 2048);

    // layer 1 recurrence
    lstm_recur_mma<256, true><<<128, 256, R1_SMEM>>>(xg1, Whh1, h1, out1, bar1, 512);

    // layer 2 input projection
    gemm_tf32_perm<<<dim3(512 / 128, M / 128), 256, GEMM_SMEM>>>(
        out1, w2cv, bih2, bhh2, xg2, M, 512, 256);

    // layer 2 recurrence
    lstm_recur_mma<128, false><<<64, 256, R2_SMEM>>>(xg2, Whh2, h2, (float*)0, bar2, 512);

    // FC head
    fc_head<<<1, 64>>>(h2, Wfc1, bfc1, Wout, bout, outp);
}